// round 4
// baseline (speedup 1.0000x reference)
#include <cuda_runtime.h>
#include <cuda_bf16.h>
#include <cstdint>

#define Bb 32
#define Ss 4096
#define Hh 512
#define Ee 512
#define NEGV -1000000000.0f

// ---------------- scratch ----------------
__device__ float g_qpc[Bb * Hh];
__device__ float g_ctxpart[8 * Bb * Ee];
__device__ __align__(16) __nv_bfloat16 g_wkt_hi[Hh * Ee];      // Wk^T hi [h][e]
__device__ __align__(16) __nv_bfloat16 g_wkt_lo[Hh * Ee];      // Wk^T lo [h][e]
__device__ __align__(16) __nv_bfloat16 g_kh[Bb * Ss * Ee];     // keys hi
__device__ __align__(16) __nv_bfloat16 g_kl[Bb * Ss * Ee];     // keys lo

// ---------------- helpers ----------------
__device__ __forceinline__ uint32_t smem_u32(const void* p) {
    uint32_t a;
    asm("{ .reg .u64 t; cvta.to.shared.u64 t, %1; cvt.u32.u64 %0, t; }" : "=r"(a) : "l"(p));
    return a;
}
__device__ __forceinline__ uint32_t swz(uint32_t off) { return off ^ ((off >> 3) & 0x70); }

__device__ __forceinline__ float tanh_fast(float x) {
    float e = __expf(2.0f * x);
    return 1.0f - __fdividef(2.0f, e + 1.0f);
}
__device__ __forceinline__ void ldmx4(uint32_t& r0, uint32_t& r1, uint32_t& r2, uint32_t& r3,
                                      uint32_t addr) {
    asm volatile("ldmatrix.sync.aligned.m8n8.x4.shared.b16 {%0,%1,%2,%3}, [%4];"
                 : "=r"(r0), "=r"(r1), "=r"(r2), "=r"(r3) : "r"(addr));
}
__device__ __forceinline__ void mma16816(float* d, const uint32_t* a, uint32_t b0, uint32_t b1) {
    asm volatile(
        "mma.sync.aligned.m16n8k16.row.col.f32.bf16.bf16.f32 "
        "{%0,%1,%2,%3}, {%4,%5,%6,%7}, {%8,%9}, {%0,%1,%2,%3};"
        : "+f"(d[0]), "+f"(d[1]), "+f"(d[2]), "+f"(d[3])
        : "r"(a[0]), "r"(a[1]), "r"(a[2]), "r"(a[3]), "r"(b0), "r"(b1));
}
#define CP_ASYNC16(dst, src) \
    asm volatile("cp.async.cg.shared.global [%0], [%1], 16;" :: "r"(dst), "l"(src))
#define CP_COMMIT() asm volatile("cp.async.commit_group;" ::: "memory")
#define CP_WAIT1() asm volatile("cp.async.wait_group 1;" ::: "memory")

// ---------------- K_cvt: keys fp32 -> bf16 hi/lo ----------------
__global__ void keys_cvt_kernel(const float* __restrict__ keys) {
    const int nthreads = gridDim.x * blockDim.x;
    int g = blockIdx.x * blockDim.x + threadIdx.x;
    const int ngroups = (Bb * Ss * Ee) / 8;
    for (; g < ngroups; g += nthreads) {
        size_t base = (size_t)g * 8;
        float4 x0 = *(const float4*)(keys + base);
        float4 x1 = *(const float4*)(keys + base + 4);
        float xs[8] = {x0.x, x0.y, x0.z, x0.w, x1.x, x1.y, x1.z, x1.w};
        union { uint4 u; __nv_bfloat16 b[8]; } vh, vl;
#pragma unroll
        for (int i = 0; i < 8; i++) {
            __nv_bfloat16 h = __float2bfloat16(xs[i]);
            vh.b[i] = h;
            vl.b[i] = __float2bfloat16(xs[i] - __bfloat162float(h));
        }
        *(uint4*)(g_kh + base) = vh.u;
        *(uint4*)(g_kl + base) = vl.u;
    }
}

// ---------------- K0: transpose+convert Wk -> bf16 hi/lo (Wkt[h][e]) ----------------
__global__ void wkt_kernel(const float* __restrict__ Wk) {
    __shared__ float t[64][65];
    int e0 = (blockIdx.x >> 3) * 64, h0 = (blockIdx.x & 7) * 64;
    int tx = threadIdx.x & 63, ty = threadIdx.x >> 6;
#pragma unroll
    for (int i = 0; i < 16; i++) {
        int r = ty + i * 4;
        t[r][tx] = Wk[(size_t)(e0 + r) * Hh + h0 + tx];
    }
    __syncthreads();
#pragma unroll
    for (int i = 0; i < 16; i++) {
        int hr = ty + i * 4;
        float x = t[tx][hr];
        __nv_bfloat16 hi = __float2bfloat16(x);
        __nv_bfloat16 lo = __float2bfloat16(x - __bfloat162float(hi));
        g_wkt_hi[(size_t)(h0 + hr) * Ee + e0 + tx] = hi;
        g_wkt_lo[(size_t)(h0 + hr) * Ee + e0 + tx] = lo;
    }
}

// ---------------- K1: q_proj + bq + bk ----------------
__global__ void qproj_kernel(const float* __restrict__ query, const float* __restrict__ Wq,
                             const float* __restrict__ bq, const float* __restrict__ bk) {
    __shared__ float qs[Hh];
    int b = blockIdx.x, h = threadIdx.x;
    qs[h] = query[b * Hh + h];
    __syncthreads();
    float acc = bq[h] + bk[h];
#pragma unroll 8
    for (int e = 0; e < Hh; e++) acc += qs[e] * Wq[e * Hh + h];
    g_qpc[b * Hh + h] = acc;
}

// ---------------- K2: mma.sync scores kernel ----------------
// CTA: M=128 rows x full H (2 N-phases of 256). 8 warps = 2(M) x 4(N), warp tile m64n64.
// Double-buffered cp.async stages; stage = Ah 16K | Al 16K | Bh 32K | Bl 32K = 96KB.
#define MT 128
#define NP 256
#define KC 64
#define STG 98304
#define SO_AH 0
#define SO_AL 16384
#define SO_BH 32768
#define SO_BL 65536
#define O_SQ (2 * STG)
#define O_SV (O_SQ + 2048)
#define O_RED (O_SV + 2048)
#define SMEM_TOTAL (O_RED + 2048)

__device__ __forceinline__ void load_stage(uint32_t smem_base, int row0, int it, int stage) {
    const int tid = threadIdx.x;
    const int p = it >> 3, kc = it & 7;
    const uint32_t sb = smem_base + stage * STG;
    // A: 128 rows x 64 k (hi, lo): 4 x 16B per thread each
#pragma unroll
    for (int j = 0; j < 4; j++) {
        int s = tid + j * 256;
        int r = s >> 3, k8 = (s & 7) * 8;
        size_t gidx = (size_t)(row0 + r) * Ee + kc * KC + k8;
        uint32_t off = swz((uint32_t)(r * 128 + k8 * 2));
        CP_ASYNC16(sb + SO_AH + off, (const char*)(g_kh + gidx));
        CP_ASYNC16(sb + SO_AL + off, (const char*)(g_kl + gidx));
    }
    // B: 256 n x 64 k (hi, lo): 8 x 16B per thread each
#pragma unroll
    for (int j = 0; j < 8; j++) {
        int s = tid + j * 256;
        int n = s >> 3, k8 = (s & 7) * 8;
        size_t gidx = (size_t)(p * NP + n) * Ee + kc * KC + k8;
        uint32_t off = swz((uint32_t)(n * 128 + k8 * 2));
        CP_ASYNC16(sb + SO_BH + off, (const char*)(g_wkt_hi + gidx));
        CP_ASYNC16(sb + SO_BL + off, (const char*)(g_wkt_lo + gidx));
    }
}

__global__ __launch_bounds__(256, 1) void scores_mma_kernel(
    const int* __restrict__ mask, const float* __restrict__ v,
    const float* __restrict__ bv, float* __restrict__ scores) {
    extern __shared__ char smem[];
    const uint32_t smem_base = smem_u32(smem);
    const int tid = threadIdx.x;
    const int lane = tid & 31;
    const int wid = tid >> 5;
    const int wm = wid >> 2;          // 0..1
    const int wn = wid & 3;           // 0..3
    const int m_off = wm * 64;
    const int n_off = wn * 64;
    const int row0 = blockIdx.x * MT;
    const int b = row0 >> 12;

    float* sq = (float*)(smem + O_SQ);
    float* sv = (float*)(smem + O_SV);
    sq[tid] = g_qpc[b * Hh + tid];
    sq[tid + 256] = g_qpc[b * Hh + tid + 256];
    sv[tid] = v[tid];
    sv[tid + 256] = v[tid + 256];

    const int jm = lane >> 3;
    const int rr = lane & 7;

    float rs[8];
#pragma unroll
    for (int i = 0; i < 8; i++) rs[i] = 0.f;

    load_stage(smem_base, row0, 0, 0);
    CP_COMMIT();
    load_stage(smem_base, row0, 1, 1);
    CP_COMMIT();

    float acc[4][8][4];
#pragma unroll
    for (int f = 0; f < 4; f++)
#pragma unroll
        for (int j = 0; j < 8; j++)
#pragma unroll
            for (int q = 0; q < 4; q++) acc[f][j][q] = 0.f;

    for (int it = 0; it < 16; it++) {
        const int p = it >> 3, kc = it & 7;
        const int stage = it & 1;
        CP_WAIT1();
        __syncthreads();

        const uint32_t sb = smem_base + stage * STG;
        const uint32_t ah_base = sb + SO_AH;
        const uint32_t al_base = sb + SO_AL;
        const uint32_t bh_base = sb + SO_BH;
        const uint32_t bl_base = sb + SO_BL;

#pragma unroll
        for (int kk = 0; kk < 4; kk++) {
            const int k0l = kk * 16;
            uint32_t ahi[4][4], alo[4][4];
#pragma unroll
            for (int f = 0; f < 4; f++) {
                uint32_t aoff = swz((uint32_t)((m_off + f * 16 + (jm & 1) * 8 + rr) * 128 +
                                               (k0l + (jm >> 1) * 8) * 2));
                ldmx4(ahi[f][0], ahi[f][1], ahi[f][2], ahi[f][3], ah_base + aoff);
                ldmx4(alo[f][0], alo[f][1], alo[f][2], alo[f][3], al_base + aoff);
            }
#pragma unroll
            for (int q = 0; q < 4; q++) {
                const int frag0 = 2 * q;
                uint32_t boff = swz((uint32_t)((n_off + (frag0 + (jm >> 1)) * 8 + rr) * 128 +
                                               (k0l + (jm & 1) * 8) * 2));
                uint32_t bh0, bh1, bh2, bh3, bl0, bl1, bl2, bl3;
                ldmx4(bh0, bh1, bh2, bh3, bh_base + boff);
                ldmx4(bl0, bl1, bl2, bl3, bl_base + boff);
#pragma unroll
                for (int f = 0; f < 4; f++) {
                    mma16816(acc[f][frag0], ahi[f], bh0, bh1);
                    mma16816(acc[f][frag0], ahi[f], bl0, bl1);
                    mma16816(acc[f][frag0], alo[f], bh0, bh1);
                    mma16816(acc[f][frag0 + 1], ahi[f], bh2, bh3);
                    mma16816(acc[f][frag0 + 1], ahi[f], bl2, bl3);
                    mma16816(acc[f][frag0 + 1], alo[f], bh2, bh3);
                }
            }
        }
        __syncthreads();
        if (it + 2 < 16) load_stage(smem_base, row0, it + 2, stage);
        CP_COMMIT();

        if (kc == 7) {
            // fold this phase's accumulators into row sums, reset acc
#pragma unroll
            for (int f = 0; f < 4; f++)
#pragma unroll
                for (int j = 0; j < 8; j++) {
                    const int col = p * NP + n_off + j * 8 + (lane & 3) * 2;
                    const float q0 = sq[col], q1 = sq[col + 1];
                    const float v0 = sv[col], v1 = sv[col + 1];
                    rs[f * 2 + 0] += tanh_fast(acc[f][j][0] + q0) * v0 +
                                     tanh_fast(acc[f][j][1] + q1) * v1;
                    rs[f * 2 + 1] += tanh_fast(acc[f][j][2] + q0) * v0 +
                                     tanh_fast(acc[f][j][3] + q1) * v1;
                    acc[f][j][0] = acc[f][j][1] = acc[f][j][2] = acc[f][j][3] = 0.f;
                }
        }
    }

    // reduce across the 4 lanes sharing a row, then across the 4 N-warps
#pragma unroll
    for (int i = 0; i < 8; i++) {
        rs[i] += __shfl_xor_sync(~0u, rs[i], 1);
        rs[i] += __shfl_xor_sync(~0u, rs[i], 2);
    }
    float* red = (float*)(smem + O_RED);   // [128][4]
    if ((lane & 3) == 0) {
#pragma unroll
        for (int f = 0; f < 4; f++)
#pragma unroll
            for (int h = 0; h < 2; h++) {
                int r = m_off + f * 16 + h * 8 + (lane >> 2);
                red[r * 4 + wn] = rs[f * 2 + h];
            }
    }
    __syncthreads();
    if (tid < MT) {
        float s = red[tid * 4] + red[tid * 4 + 1] + red[tid * 4 + 2] + red[tid * 4 + 3] + bv[0];
        int grow = row0 + tid;
        s = (mask[grow] == 0) ? NEGV : s;
        scores[grow] = s;
    }
}

// ---------------- K3: softmax ----------------
__global__ void softmax_kernel(float* __restrict__ attn) {
    __shared__ float buf[Ss];
    __shared__ float rtmp[32];
    __shared__ float rowstat;
    int b = blockIdx.x, tid = threadIdx.x;
    float* row = attn + (size_t)b * Ss;
    float lmax = -3.4e38f;
#pragma unroll
    for (int i = 0; i < Ss / 256; i++) {
        float x = row[tid + i * 256];
        buf[tid + i * 256] = x;
        lmax = fmaxf(lmax, x);
    }
#pragma unroll
    for (int o = 16; o; o >>= 1) lmax = fmaxf(lmax, __shfl_xor_sync(~0u, lmax, o));
    if ((tid & 31) == 0) rtmp[tid >> 5] = lmax;
    __syncthreads();
    if (tid == 0) {
        float m = rtmp[0];
        for (int w = 1; w < 8; w++) m = fmaxf(m, rtmp[w]);
        rowstat = m;
    }
    __syncthreads();
    float m = rowstat;
    float lsum = 0.0f;
#pragma unroll
    for (int i = 0; i < Ss / 256; i++) {
        float e = __expf(buf[tid + i * 256] - m);
        buf[tid + i * 256] = e;
        lsum += e;
    }
#pragma unroll
    for (int o = 16; o; o >>= 1) lsum += __shfl_xor_sync(~0u, lsum, o);
    __syncthreads();
    if ((tid & 31) == 0) rtmp[tid >> 5] = lsum;
    __syncthreads();
    if (tid == 0) {
        float s = 0.0f;
        for (int w = 0; w < 8; w++) s += rtmp[w];
        rowstat = 1.0f / s;
    }
    __syncthreads();
    float inv = rowstat;
#pragma unroll
    for (int i = 0; i < Ss / 256; i++) row[tid + i * 256] = buf[tid + i * 256] * inv;
}

// ---------------- K4/K5: context ----------------
__global__ void context_partial_kernel(const float* __restrict__ keys,
                                       const float* __restrict__ attn) {
    __shared__ float aw[512];
    int b = blockIdx.y;
    int chunk = blockIdx.x;  // 0..7
    int s0 = chunk * 512;
    int e = threadIdx.x;     // 512
    aw[e] = attn[(size_t)b * Ss + s0 + e];
    __syncthreads();
    const float* kp = keys + ((size_t)b * Ss + s0) * Ee + e;
    float acc = 0.0f;
#pragma unroll 8
    for (int s = 0; s < 512; s++) acc += aw[s] * kp[(size_t)s * Ee];
    g_ctxpart[(chunk * Bb + b) * Ee + e] = acc;
}

__global__ void context_reduce_kernel(float* __restrict__ ctx) {
    int b = blockIdx.x, e = threadIdx.x;
    float acc = 0.0f;
#pragma unroll
    for (int c = 0; c < 8; c++) acc += g_ctxpart[(c * Bb + b) * Ee + e];
    ctx[b * Ee + e] = acc;
}

extern "C" void kernel_launch(void* const* d_in, const int* in_sizes, int n_in,
                              void* d_out, int out_size) {
    const float* query = (const float*)d_in[0];
    const float* keys  = (const float*)d_in[1];
    const int*   mask  = (const int*)d_in[2];
    const float* Wq    = (const float*)d_in[3];
    const float* bq    = (const float*)d_in[4];
    const float* Wk    = (const float*)d_in[5];
    const float* bk    = (const float*)d_in[6];
    const float* v     = (const float*)d_in[7];
    const float* bv    = (const float*)d_in[8];

    float* out  = (float*)d_out;
    float* ctx  = out;
    float* attn = out + Bb * Ee;

    cudaFuncSetAttribute(scores_mma_kernel, cudaFuncAttributeMaxDynamicSharedMemorySize,
                         SMEM_TOTAL);

    keys_cvt_kernel<<<1024, 256>>>(keys);
    wkt_kernel<<<64, 256>>>(Wk);
    qproj_kernel<<<Bb, Hh>>>(query, Wq, bq, bk);
    scores_mma_kernel<<<(Bb * Ss) / MT, 256, SMEM_TOTAL>>>(mask, v, bv, attn);
    softmax_kernel<<<Bb, 256>>>(attn);
    {
        dim3 grid(8, Bb);
        context_partial_kernel<<<grid, 512>>>(keys, attn);
    }
    context_reduce_kernel<<<Bb, Ee>>>(ctx);
}

// round 6
// speedup vs baseline: 1.3098x; 1.3098x over previous
#include <cuda_runtime.h>
#include <cuda_bf16.h>
#include <cstdint>

#define Bb 32
#define Ss 4096
#define Hh 512
#define Ee 512
#define NEGV -1000000000.0f

// ---------------- scratch ----------------
__device__ float g_qpc[Bb * Hh];
__device__ float g_ctxpart[16 * Bb * Ee];
__device__ __align__(16) __nv_bfloat16 g_wkt_hi[Hh * Ee];   // Wk^T hi [h][e]
__device__ __align__(16) __nv_bfloat16 g_wkt_lo[Hh * Ee];   // Wk^T lo [h][e]

// ---------------- helpers ----------------
__device__ __forceinline__ uint32_t smem_u32(const void* p) {
    uint32_t a;
    asm("{ .reg .u64 t; cvta.to.shared.u64 t, %1; cvt.u32.u64 %0, t; }" : "=r"(a) : "l"(p));
    return a;
}
__device__ __forceinline__ uint32_t swz(uint32_t off) { return off ^ ((off >> 3) & 0x70); }

__device__ __forceinline__ float tanh_fast(float x) {
    float e = __expf(2.0f * x);
    return 1.0f - __fdividef(2.0f, e + 1.0f);
}
__device__ __forceinline__ void ldmx4(uint32_t& r0, uint32_t& r1, uint32_t& r2, uint32_t& r3,
                                      uint32_t addr) {
    asm volatile("ldmatrix.sync.aligned.m8n8.x4.shared.b16 {%0,%1,%2,%3}, [%4];"
                 : "=r"(r0), "=r"(r1), "=r"(r2), "=r"(r3) : "r"(addr));
}
__device__ __forceinline__ void mma16816(float* d, const uint32_t* a, uint32_t b0, uint32_t b1) {
    asm volatile(
        "mma.sync.aligned.m16n8k16.row.col.f32.bf16.bf16.f32 "
        "{%0,%1,%2,%3}, {%4,%5,%6,%7}, {%8,%9}, {%0,%1,%2,%3};"
        : "+f"(d[0]), "+f"(d[1]), "+f"(d[2]), "+f"(d[3])
        : "r"(a[0]), "r"(a[1]), "r"(a[2]), "r"(a[3]), "r"(b0), "r"(b1));
}
#define CP_ASYNC16(dst, src) \
    asm volatile("cp.async.cg.shared.global [%0], [%1], 16;" :: "r"(dst), "l"(src))
#define CP_COMMIT() asm volatile("cp.async.commit_group;" ::: "memory")
#define CP_WAIT1() asm volatile("cp.async.wait_group 1;" ::: "memory")

// ---------------- K0: transpose+convert Wk -> bf16 hi/lo (Wkt[h][e]) ----------------
__global__ void wkt_kernel(const float* __restrict__ Wk) {
    __shared__ float t[64][65];
    int e0 = (blockIdx.x >> 3) * 64, h0 = (blockIdx.x & 7) * 64;
    int tx = threadIdx.x & 63, ty = threadIdx.x >> 6;
#pragma unroll
    for (int i = 0; i < 16; i++) {
        int r = ty + i * 4;
        t[r][tx] = Wk[(size_t)(e0 + r) * Hh + h0 + tx];
    }
    __syncthreads();
#pragma unroll
    for (int i = 0; i < 16; i++) {
        int hr = ty + i * 4;
        float x = t[tx][hr];
        __nv_bfloat16 hi = __float2bfloat16(x);
        __nv_bfloat16 lo = __float2bfloat16(x - __bfloat162float(hi));
        g_wkt_hi[(size_t)(h0 + hr) * Ee + e0 + tx] = hi;
        g_wkt_lo[(size_t)(h0 + hr) * Ee + e0 + tx] = lo;
    }
}

// ---------------- K1: q_proj + bq + bk (128 blocks) ----------------
__global__ void qproj_kernel(const float* __restrict__ query, const float* __restrict__ Wq,
                             const float* __restrict__ bq, const float* __restrict__ bk) {
    __shared__ float qs[Hh];
    int b = blockIdx.x >> 2;
    int h = (blockIdx.x & 3) * 128 + threadIdx.x;
#pragma unroll
    for (int i = 0; i < 4; i++) qs[threadIdx.x + i * 128] = query[b * Hh + threadIdx.x + i * 128];
    __syncthreads();
    float acc = bq[h] + bk[h];
#pragma unroll 8
    for (int e = 0; e < Hh; e++) acc += qs[e] * Wq[e * Hh + h];
    g_qpc[b * Hh + h] = acc;
}

// ---------------- K2: mma.sync scores kernel ----------------
// CTA: M=128 x H via 4 N-phases of 128. 8 warps = 4(M) x 2(N), warp tile m32n64.
// Pipeline: cp.async raw A fp32 + bf16 B (2-deep); A converted smem->smem one chunk ahead.
#define MT 128
#define NP 128
#define KC 64
#define NIT 32                    // 4 phases x 8 k-chunks
#define O_ARAW 0                  // 2 x 32KB raw fp32 A
#define O_ACV 65536               // 2 x (Ah 16K | Al 16K)
#define O_B 131072                // 2 x (Bh 16K | Bl 16K)
#define O_SQ 196608
#define O_SV (O_SQ + 2048)
#define O_RED (O_SV + 2048)
#define SMEM_TOTAL (O_RED + 1024)

__device__ __forceinline__ void issue_cp(uint32_t smem_base, const float* __restrict__ keys,
                                         int row0, int it) {
    const int tid = threadIdx.x;
    const int p = it >> 3, kc = it & 7;
    const int st = it & 1;
    const uint32_t araw = smem_base + O_ARAW + st * 32768;
    const uint32_t bh = smem_base + O_B + st * 32768;
    const uint32_t bl = bh + 16384;
    // raw A: 128 rows x 64 fp32 = 2048 x 16B, 8/thread
#pragma unroll
    for (int j = 0; j < 8; j++) {
        int s = tid + j * 256;
        int r = s >> 4, kq = (s & 15) * 4;
        const char* src = (const char*)(keys + (size_t)(row0 + r) * Ee + kc * KC + kq);
        CP_ASYNC16(araw + r * 256 + kq * 4, src);
    }
    // B: 128 n x 64 k bf16 hi/lo, 1024 x 16B each, 4/thread each
#pragma unroll
    for (int j = 0; j < 4; j++) {
        int s = tid + j * 256;
        int n = s >> 3, k8 = (s & 7) * 8;
        size_t gidx = (size_t)(p * NP + n) * Ee + kc * KC + k8;
        uint32_t off = swz((uint32_t)(n * 128 + k8 * 2));
        CP_ASYNC16(bh + off, (const char*)(g_wkt_hi + gidx));
        CP_ASYNC16(bl + off, (const char*)(g_wkt_lo + gidx));
    }
}

__device__ __forceinline__ void convert_A(uint32_t smem_base, char* smem, int it) {
    const int tid = threadIdx.x;
    const int st = it & 1;
    const char* raw = smem + O_ARAW + st * 32768;
    char* Ah = smem + O_ACV + st * 32768;
    char* Al = Ah + 16384;
#pragma unroll
    for (int j = 0; j < 4; j++) {
        int s = tid + j * 256;
        int r = s >> 3, k8 = (s & 7) * 8;
        const float4* rp = (const float4*)(raw + r * 256 + k8 * 4);
        float4 x0 = rp[0], x1 = rp[1];
        float xs[8] = {x0.x, x0.y, x0.z, x0.w, x1.x, x1.y, x1.z, x1.w};
        union { uint4 u; __nv_bfloat16 b[8]; } vh, vl;
#pragma unroll
        for (int i = 0; i < 8; i++) {
            __nv_bfloat16 h = __float2bfloat16(xs[i]);
            vh.b[i] = h;
            vl.b[i] = __float2bfloat16(xs[i] - __bfloat162float(h));
        }
        uint32_t off = swz((uint32_t)(r * 128 + k8 * 2));
        *(uint4*)(Ah + off) = vh.u;
        *(uint4*)(Al + off) = vl.u;
    }
}

__global__ __launch_bounds__(256, 1) void scores_mma_kernel(
    const float* __restrict__ keys, const int* __restrict__ mask,
    const float* __restrict__ v, const float* __restrict__ bv,
    float* __restrict__ scores) {
    extern __shared__ char smem[];
    const uint32_t smem_base = smem_u32(smem);
    const int tid = threadIdx.x;
    const int lane = tid & 31;
    const int wid = tid >> 5;
    const int wm = wid >> 1;          // 0..3
    const int wn = wid & 1;           // 0..1
    const int m_off = wm * 32;
    const int n_off = wn * 64;
    const int row0 = blockIdx.x * MT;
    const int b = row0 >> 12;

    float* sq = (float*)(smem + O_SQ);
    float* sv = (float*)(smem + O_SV);
    sq[tid] = g_qpc[b * Hh + tid];
    sq[tid + 256] = g_qpc[b * Hh + tid + 256];
    sv[tid] = v[tid];
    sv[tid + 256] = v[tid + 256];

    const int jm = lane >> 3;
    const int rr = lane & 7;

    float rs[4] = {0.f, 0.f, 0.f, 0.f};
    float acc[2][8][4];
#pragma unroll
    for (int f = 0; f < 2; f++)
#pragma unroll
        for (int j = 0; j < 8; j++)
#pragma unroll
            for (int q = 0; q < 4; q++) acc[f][j][q] = 0.f;

    // prologue: load chunk 0 and 1; convert chunk 0
    issue_cp(smem_base, keys, row0, 0);
    CP_COMMIT();
    issue_cp(smem_base, keys, row0, 1);
    CP_COMMIT();
    CP_WAIT1();
    __syncthreads();
    convert_A(smem_base, smem, 0);
    __syncthreads();

    for (int it = 0; it < NIT; it++) {
        const int p = it >> 3, kc = it & 7;
        const int st = it & 1;
        const uint32_t ah_base = smem_base + O_ACV + st * 32768;
        const uint32_t al_base = ah_base + 16384;
        const uint32_t bh_base = smem_base + O_B + st * 32768;
        const uint32_t bl_base = bh_base + 16384;

        // ---- MMAs on chunk it ----
#pragma unroll
        for (int kk = 0; kk < 4; kk++) {
            const int k0l = kk * 16;
            uint32_t ahi[2][4], alo[2][4];
#pragma unroll
            for (int f = 0; f < 2; f++) {
                uint32_t aoff = swz((uint32_t)((m_off + f * 16 + (jm & 1) * 8 + rr) * 128 +
                                               (k0l + (jm >> 1) * 8) * 2));
                ldmx4(ahi[f][0], ahi[f][1], ahi[f][2], ahi[f][3], ah_base + aoff);
                ldmx4(alo[f][0], alo[f][1], alo[f][2], alo[f][3], al_base + aoff);
            }
#pragma unroll
            for (int q = 0; q < 4; q++) {
                const int frag0 = 2 * q;
                uint32_t boff = swz((uint32_t)((n_off + (frag0 + (jm >> 1)) * 8 + rr) * 128 +
                                               (k0l + (jm & 1) * 8) * 2));
                uint32_t bh0, bh1, bh2, bh3, bl0, bl1, bl2, bl3;
                ldmx4(bh0, bh1, bh2, bh3, bh_base + boff);
                ldmx4(bl0, bl1, bl2, bl3, bl_base + boff);
#pragma unroll
                for (int f = 0; f < 2; f++) {
                    mma16816(acc[f][frag0], ahi[f], bh0, bh1);
                    mma16816(acc[f][frag0], ahi[f], bl0, bl1);
                    mma16816(acc[f][frag0], alo[f], bh0, bh1);
                    mma16816(acc[f][frag0 + 1], ahi[f], bh2, bh3);
                    mma16816(acc[f][frag0 + 1], ahi[f], bl2, bl3);
                    mma16816(acc[f][frag0 + 1], alo[f], bh2, bh3);
                }
            }
        }
        __syncthreads();                      // all warps done reading stage st

        // ---- issue loads for chunk it+2 into stage st (now free) ----
        if (it + 2 < NIT) issue_cp(smem_base, keys, row0, it + 2);
        CP_COMMIT();

        // ---- wait chunk it+1 arrival; convert its A ----
        if (it + 1 < NIT) {
            CP_WAIT1();
            __syncthreads();                  // arrivals visible to all
            convert_A(smem_base, smem, it + 1);
        }
        __syncthreads();                      // conv visible before next iter's MMAs

        // ---- end of phase: fold accumulators into row sums ----
        if (kc == 7) {
#pragma unroll
            for (int f = 0; f < 2; f++)
#pragma unroll
                for (int j = 0; j < 8; j++) {
                    const int col = p * NP + n_off + j * 8 + (lane & 3) * 2;
                    const float q0 = sq[col], q1 = sq[col + 1];
                    const float v0 = sv[col], v1 = sv[col + 1];
                    rs[f * 2 + 0] += tanh_fast(acc[f][j][0] + q0) * v0 +
                                     tanh_fast(acc[f][j][1] + q1) * v1;
                    rs[f * 2 + 1] += tanh_fast(acc[f][j][2] + q0) * v0 +
                                     tanh_fast(acc[f][j][3] + q1) * v1;
                    acc[f][j][0] = acc[f][j][1] = acc[f][j][2] = acc[f][j][3] = 0.f;
                }
        }
    }

    // reduce across 4 lanes sharing a row, then across 2 N-warps
#pragma unroll
    for (int i = 0; i < 4; i++) {
        rs[i] += __shfl_xor_sync(~0u, rs[i], 1);
        rs[i] += __shfl_xor_sync(~0u, rs[i], 2);
    }
    float* red = (float*)(smem + O_RED);   // [128][2]
    if ((lane & 3) == 0) {
#pragma unroll
        for (int i = 0; i < 4; i++) {
            int r = m_off + (i >> 1) * 16 + (i & 1) * 8 + (lane >> 2);
            red[r * 2 + wn] = rs[i];
        }
    }
    __syncthreads();
    if (tid < MT) {
        float s = red[tid * 2] + red[tid * 2 + 1] + bv[0];
        int grow = row0 + tid;
        s = (mask[grow] == 0) ? NEGV : s;
        scores[grow] = s;
    }
}

// ---------------- K3: softmax ----------------
__global__ void softmax_kernel(float* __restrict__ attn) {
    __shared__ float buf[Ss];
    __shared__ float rtmp[32];
    __shared__ float rowstat;
    int b = blockIdx.x, tid = threadIdx.x;
    float* row = attn + (size_t)b * Ss;
    float lmax = -3.4e38f;
#pragma unroll
    for (int i = 0; i < Ss / 256; i++) {
        float x = row[tid + i * 256];
        buf[tid + i * 256] = x;
        lmax = fmaxf(lmax, x);
    }
#pragma unroll
    for (int o = 16; o; o >>= 1) lmax = fmaxf(lmax, __shfl_xor_sync(~0u, lmax, o));
    if ((tid & 31) == 0) rtmp[tid >> 5] = lmax;
    __syncthreads();
    if (tid == 0) {
        float m = rtmp[0];
        for (int w = 1; w < 8; w++) m = fmaxf(m, rtmp[w]);
        rowstat = m;
    }
    __syncthreads();
    float m = rowstat;
    float lsum = 0.0f;
#pragma unroll
    for (int i = 0; i < Ss / 256; i++) {
        float e = __expf(buf[tid + i * 256] - m);
        buf[tid + i * 256] = e;
        lsum += e;
    }
#pragma unroll
    for (int o = 16; o; o >>= 1) lsum += __shfl_xor_sync(~0u, lsum, o);
    __syncthreads();
    if ((tid & 31) == 0) rtmp[tid >> 5] = lsum;
    __syncthreads();
    if (tid == 0) {
        float s = 0.0f;
        for (int w = 0; w < 8; w++) s += rtmp[w];
        rowstat = 1.0f / s;
    }
    __syncthreads();
    float inv = rowstat;
#pragma unroll
    for (int i = 0; i < Ss / 256; i++) row[tid + i * 256] = buf[tid + i * 256] * inv;
}

// ---------------- K4/K5: context ----------------
__global__ void context_partial_kernel(const float* __restrict__ keys,
                                       const float* __restrict__ attn) {
    __shared__ float aw[256];
    int b = blockIdx.y, chunk = blockIdx.x;   // 16 chunks of 256
    int s0 = chunk * 256;
    int tid = threadIdx.x;                    // 512
    if (tid < 256) aw[tid] = attn[(size_t)b * Ss + s0 + tid];
    __syncthreads();
    const float* kp = keys + ((size_t)b * Ss + s0) * Ee + tid;
    float acc = 0.0f;
#pragma unroll 8
    for (int s = 0; s < 256; s++) acc += aw[s] * kp[(size_t)s * Ee];
    g_ctxpart[(chunk * Bb + b) * Ee + tid] = acc;
}

__global__ void context_reduce_kernel(float* __restrict__ ctx) {
    int b = blockIdx.x, e = threadIdx.x;
    float acc = 0.0f;
#pragma unroll
    for (int c = 0; c < 16; c++) acc += g_ctxpart[(c * Bb + b) * Ee + e];
    ctx[b * Ee + e] = acc;
}

extern "C" void kernel_launch(void* const* d_in, const int* in_sizes, int n_in,
                              void* d_out, int out_size) {
    const float* query = (const float*)d_in[0];
    const float* keys  = (const float*)d_in[1];
    const int*   mask  = (const int*)d_in[2];
    const float* Wq    = (const float*)d_in[3];
    const float* bq    = (const float*)d_in[4];
    const float* Wk    = (const float*)d_in[5];
    const float* bk    = (const float*)d_in[6];
    const float* v     = (const float*)d_in[7];
    const float* bv    = (const float*)d_in[8];

    float* out  = (float*)d_out;
    float* ctx  = out;
    float* attn = out + Bb * Ee;

    cudaFuncSetAttribute(scores_mma_kernel, cudaFuncAttributeMaxDynamicSharedMemorySize,
                         SMEM_TOTAL);

    wkt_kernel<<<64, 256>>>(Wk);
    qproj_kernel<<<Bb * 4, 128>>>(query, Wq, bq, bk);
    scores_mma_kernel<<<(Bb * Ss) / MT, 256, SMEM_TOTAL>>>(keys, mask, v, bv, attn);
    softmax_kernel<<<Bb, 256>>>(attn);
    {
        dim3 grid(16, Bb);
        context_partial_kernel<<<grid, 512>>>(keys, attn);
    }
    context_reduce_kernel<<<Bb, Ee>>>(ctx);
}